// round 12
// baseline (speedup 1.0000x reference)
#include <cuda_runtime.h>

// AlignBlock on sm_103a, round 12: r11 winner (78.9us) + two bounded changes:
//  - align: rolling X register window (LDG/thread 56 -> 35, L1-wavefront bound)
//  - convsoftmax: t-tile 4 @ 64 thr, 256 blocks (fill all 148 SMs)
//  - chanmix, corr: unchanged r10/r11 pieces
// Shapes: B=2, C=H=64, T=512, F=64, DMAX=32. All fp32.

#define Bn 2
#define Cn 64
#define Hn 64
#define Tn 512
#define Fn 64
#define Dn 32

__device__ float g_Q[Bn * Hn * Tn * Fn];
__device__ float g_K[Bn * Hn * Tn * Fn];
__device__ float g_V[Bn * Hn * Tn * Dn];
__device__ float g_A[Bn * Tn * Dn];

// ---------------------------------------------------------------------------
// Kernel 1: channel mix for Q AND K (merged). (r10/r11 version, at FMA floor)
// ---------------------------------------------------------------------------
__global__ void __launch_bounds__(256) k_chanmix(const float* __restrict__ xm,
                                                 const float* __restrict__ wm,
                                                 const float* __restrict__ bm,
                                                 const float* __restrict__ xr,
                                                 const float* __restrict__ wr,
                                                 const float* __restrict__ br) {
    const int tid = threadIdx.x;
    const int which = blockIdx.x >> 10;
    const int rem = blockIdx.x & 1023;
    const int b = rem >> 9;
    const int t = rem & 511;

    const float* x    = which ? xr : xm;
    const float* w    = which ? wr : wm;
    const float* bias = which ? br : bm;
    float* out        = which ? g_K : g_Q;

    __shared__ float xs[64][68];        // [c][f]
    __shared__ float ws[64][68];        // [h][c]  (natural)

#pragma unroll
    for (int it = 0; it < 4; it++) {
        int idx = tid + it * 256;
        int q4 = (idx & 15) * 4;
        int r  = idx >> 4;
        *(float4*)&xs[r][q4] =
            *(const float4*)&x[((b * 64 + r) * 512 + t) * 64 + q4];
        *(float4*)&ws[r][q4] = *(const float4*)&w[r * 64 + q4];
    }
    __syncthreads();

    const int f0 = (tid & 15) * 4;
    const int h0 = (tid >> 4) * 4;

    float4 acc[4];
#pragma unroll
    for (int a = 0; a < 4; a++) acc[a] = make_float4(0.f, 0.f, 0.f, 0.f);

#pragma unroll 8
    for (int c = 0; c < 64; c++) {
        float4 xv = *(const float4*)&xs[c][f0];
        float w0 = ws[h0 + 0][c];
        float w1 = ws[h0 + 1][c];
        float w2 = ws[h0 + 2][c];
        float w3 = ws[h0 + 3][c];
        acc[0].x += w0 * xv.x; acc[0].y += w0 * xv.y;
        acc[0].z += w0 * xv.z; acc[0].w += w0 * xv.w;
        acc[1].x += w1 * xv.x; acc[1].y += w1 * xv.y;
        acc[1].z += w1 * xv.z; acc[1].w += w1 * xv.w;
        acc[2].x += w2 * xv.x; acc[2].y += w2 * xv.y;
        acc[2].z += w2 * xv.z; acc[2].w += w2 * xv.w;
        acc[3].x += w3 * xv.x; acc[3].y += w3 * xv.y;
        acc[3].z += w3 * xv.z; acc[3].w += w3 * xv.w;
    }

#pragma unroll
    for (int a = 0; a < 4; a++) {
        float bb = __ldg(&bias[h0 + a]);
        float4 r = acc[a];
        r.x += bb; r.y += bb; r.z += bb; r.w += bb;
        *(float4*)&out[((b * 64 + h0 + a) * 512 + t) * 64 + f0] = r;
    }
}

// ---------------------------------------------------------------------------
// Kernel 2: banded correlation (r9-r11 version).
// ---------------------------------------------------------------------------
__global__ void __launch_bounds__(128) k_corr() {
    const int tid = threadIdx.x;
    const int warp = tid >> 5, lane = tid & 31;
    const int t0 = (blockIdx.x & 7) * 64;
    const int h  = (blockIdx.x >> 3) & 63;
    const int b  = blockIdx.x >> 9;

    __shared__ float Qs[64][68];    // [f][i]
    __shared__ float Ks[64][100];   // [f][r]

    const float* qg = g_Q + ((b * 64 + h) * 512 + t0) * 64;
    const float* kg = g_K + ((b * 64 + h) * 512) * 64;

#pragma unroll
    for (int it = 0; it < 4; it++) {
        int fq = warp * 4 + it;
#pragma unroll
        for (int sub = 0; sub < 2; sub++) {
            int i = lane + sub * 32;
            float4 v = *(const float4*)&qg[i * 64 + fq * 4];
            Qs[4 * fq + 0][i] = v.x;
            Qs[4 * fq + 1][i] = v.y;
            Qs[4 * fq + 2][i] = v.z;
            Qs[4 * fq + 3][i] = v.w;
        }
    }
#pragma unroll
    for (int it = 0; it < 4; it++) {
        int fq = warp * 4 + it;
#pragma unroll
        for (int sub = 0; sub < 3; sub++) {
            int r = lane + sub * 32;
            if (r < 95) {
                int tr = t0 - 31 + r;
                float4 v = make_float4(0.f, 0.f, 0.f, 0.f);
                if (tr >= 0) v = *(const float4*)&kg[tr * 64 + fq * 4];
                Ks[4 * fq + 0][r] = v.x;
                Ks[4 * fq + 1][r] = v.y;
                Ks[4 * fq + 2][r] = v.z;
                Ks[4 * fq + 3][r] = v.w;
            }
        }
    }
    __syncthreads();

    const int d0 = (tid & 7) * 4;
    const int i0 = (tid >> 3) * 4;

    float acc[4][4];
#pragma unroll
    for (int a = 0; a < 4; a++)
#pragma unroll
        for (int e = 0; e < 4; e++) acc[a][e] = 0.f;

#pragma unroll 8
    for (int f = 0; f < 64; f++) {
        float4 q4 = *(const float4*)&Qs[f][i0];
        float4 k0 = *(const float4*)&Ks[f][i0 + d0];
        float4 k1 = *(const float4*)&Ks[f][i0 + d0 + 4];
        float qq[4] = {q4.x, q4.y, q4.z, q4.w};
        float kk[8] = {k0.x, k0.y, k0.z, k0.w, k1.x, k1.y, k1.z, k1.w};
#pragma unroll
        for (int a = 0; a < 4; a++)
#pragma unroll
            for (int e = 0; e < 4; e++)
                acc[a][e] += qq[a] * kk[a + e];
    }

    float* vg = g_V + ((b * 64 + h) * 512 + t0) * 32;
#pragma unroll
    for (int a = 0; a < 4; a++) {
        float4 r = make_float4(acc[a][0] * 0.125f, acc[a][1] * 0.125f,
                               acc[a][2] * 0.125f, acc[a][3] * 0.125f);
        *(float4*)&vg[(i0 + a) * 32 + d0] = r;
    }
}

// ---------------------------------------------------------------------------
// Kernel 3: (5,3) conv over (T,dmax) reducing H->1, + softmax over dmax.
// t-tile 4, 64 threads (2 d per thread), 256 blocks -> fills 148 SMs.
// ---------------------------------------------------------------------------
__global__ void __launch_bounds__(64) k_convsoftmax(const float* __restrict__ wconv) {
    const int tid = threadIdx.x;
    const int b  = blockIdx.x >> 7;
    const int t0 = (blockIdx.x & 127) * 4;

    __shared__ float Vs[16][8][34];   // [h_local][row r: t0-4+r][1+d], pads 0,33
    __shared__ float wcs[64][16];
    __shared__ float red[4][33];

    for (int idx = tid; idx < 960; idx += 64)
        wcs[idx / 15][idx % 15] = wconv[idx];
    for (int idx = tid; idx < 16 * 8; idx += 64) {
        Vs[idx / 8][idx % 8][0]  = 0.0f;
        Vs[idx / 8][idx % 8][33] = 0.0f;
    }

    const int tl = tid >> 4;        // 0..3
    const int d  = (tid & 15) * 2;  // even

    float accA0 = 0.f, accA1 = 0.f, accB0 = 0.f, accB1 = 0.f;

    for (int hc = 0; hc < 4; hc++) {
        __syncthreads();
        // fill 16h x 8 rows x 8 dq = 1024 float4 over 64 threads
        for (int g = tid; g < 1024; g += 64) {
            int dq = g & 7;
            int hr = g >> 3;
            int r  = hr & 7;
            int hl = hr >> 3;
#pragma unroll
            for (int hh2 = 0; hh2 < 1; hh2++) {}   // (no-op; keep structure)
            int tt = t0 - 4 + r;
            float4 v = make_float4(0.f, 0.f, 0.f, 0.f);
            if (tt >= 0)
                v = *(const float4*)&g_V[((b * 64 + hc * 16 + hl) * 512 + tt) * 32 + dq * 4];
            Vs[hl][r][1 + dq * 4 + 0] = v.x;
            Vs[hl][r][1 + dq * 4 + 1] = v.y;
            Vs[hl][r][1 + dq * 4 + 2] = v.z;
            Vs[hl][r][1 + dq * 4 + 3] = v.w;
        }
        __syncthreads();

#pragma unroll 2
        for (int hl = 0; hl < 16; hl++) {
            int hh = hc * 16 + hl;
            float wreg[16];
#pragma unroll
            for (int k4 = 0; k4 < 4; k4++) {
                float4 wv = *(const float4*)&wcs[hh][k4 * 4];
                wreg[k4 * 4 + 0] = wv.x; wreg[k4 * 4 + 1] = wv.y;
                wreg[k4 * 4 + 2] = wv.z; wreg[k4 * 4 + 3] = wv.w;
            }
#pragma unroll
            for (int i = 0; i < 5; i++) {
                float2 u = *(const float2*)&Vs[hl][tl + i][d];
                float2 v = *(const float2*)&Vs[hl][tl + i][d + 2];
                float w0 = wreg[i * 3], w1 = wreg[i * 3 + 1], w2 = wreg[i * 3 + 2];
                if (i & 1) {
                    accB0 += u.x * w0 + u.y * w1 + v.x * w2;
                    accB1 += u.y * w0 + v.x * w1 + v.y * w2;
                } else {
                    accA0 += u.x * w0 + u.y * w1 + v.x * w2;
                    accA1 += u.y * w0 + v.x * w1 + v.y * w2;
                }
            }
        }
    }

    red[tl][d]     = accA0 + accB0;
    red[tl][d + 1] = accA1 + accB1;
    __syncthreads();

    const int wd = tid >> 5, lane = tid & 31;   // 2 warps, 2 rows each
#pragma unroll
    for (int rr = 0; rr < 2; rr++) {
        int row = wd * 2 + rr;
        float v = red[row][lane];
        float mx = v;
#pragma unroll
        for (int o = 16; o > 0; o >>= 1)
            mx = fmaxf(mx, __shfl_xor_sync(0xffffffffu, mx, o));
        float e = __expf(v - mx);
        float s = e;
#pragma unroll
        for (int o = 16; o > 0; o >>= 1)
            s += __shfl_xor_sync(0xffffffffu, s, o);
        g_A[(b * 512 + t0 + row) * 32 + lane] = e / s;
    }
}

// ---------------------------------------------------------------------------
// Kernel 4: aligned[b,c,t,f] = sum_d A[b,t,d] * x_ref[b,c,t-31+d,f]
// grid = B*C*(T/32) = 2048 blocks, 128 threads. Thread tile 4t x 4f.
// X from gmem with ROLLING 7-row register window: 35 LDG.128/thread (was 56).
// ---------------------------------------------------------------------------
__device__ __forceinline__ float4 ld_row(const float* __restrict__ xg, int tg,
                                         bool guard) {
    if (guard && tg < 0) return make_float4(0.f, 0.f, 0.f, 0.f);
    return *(const float4*)&xg[tg * 64];
}

__device__ __forceinline__ void align_body(const float* __restrict__ xg,
                                           const float (*As)[36],
                                           float4* acc, int i0, int tbase,
                                           bool guard) {
    float4 xv[7];
#pragma unroll
    for (int k = 0; k < 7; k++)
        xv[k] = ld_row(xg, tbase + k, guard);

#pragma unroll
    for (int d0 = 0; d0 < 32; d0 += 4) {
        float4 av[4];
#pragma unroll
        for (int a = 0; a < 4; a++) av[a] = *(const float4*)&As[i0 + a][d0];
#pragma unroll
        for (int a = 0; a < 4; a++) {
            float aa[4] = {av[a].x, av[a].y, av[a].z, av[a].w};
#pragma unroll
            for (int dd = 0; dd < 4; dd++) {
                float4 x4 = xv[a + dd];
                acc[a].x += aa[dd] * x4.x;
                acc[a].y += aa[dd] * x4.y;
                acc[a].z += aa[dd] * x4.z;
                acc[a].w += aa[dd] * x4.w;
            }
        }
        if (d0 < 28) {
            xv[0] = xv[4]; xv[1] = xv[5]; xv[2] = xv[6];
#pragma unroll
            for (int k = 3; k < 7; k++)
                xv[k] = ld_row(xg, tbase + d0 + 4 + k, guard);
        }
    }
}

__global__ void __launch_bounds__(128) k_align(const float* __restrict__ xref,
                                               float* __restrict__ out) {
    const int tid = threadIdx.x;
    const int t0 = (blockIdx.x & 15) * 32;
    const int c  = (blockIdx.x >> 4) & 63;
    const int b  = blockIdx.x >> 10;

    __shared__ float As[32][36];

    const float* ag = g_A + (b * 512 + t0) * 32;
#pragma unroll
    for (int it = 0; it < 2; it++) {
        int idx = tid + it * 128;
        int i = idx >> 3, dq = idx & 7;
        *(float4*)&As[i][dq * 4] = *(const float4*)&ag[i * 32 + dq * 4];
    }
    __syncthreads();

    const int f0 = (tid & 15) * 4;
    const int i0 = (tid >> 4) * 4;
    const int tbase = t0 + i0 - 31;

    const float* xg = xref + ((b * 64 + c) * 512) * 64 + f0;

    float4 acc[4];
#pragma unroll
    for (int a = 0; a < 4; a++) acc[a] = make_float4(0.f, 0.f, 0.f, 0.f);

    if (t0 == 0)
        align_body(xg, As, acc, i0, tbase, true);
    else
        align_body(xg, As, acc, i0, tbase, false);

    float* og = out + ((b * 64 + c) * 512 + t0) * 64;
#pragma unroll
    for (int a = 0; a < 4; a++)
        *(float4*)&og[(i0 + a) * 64 + f0] = acc[a];
}

// ---------------------------------------------------------------------------
extern "C" void kernel_launch(void* const* d_in, const int* in_sizes, int n_in,
                              void* d_out, int out_size) {
    (void)in_sizes; (void)n_in; (void)out_size;
    const float* x_mic  = (const float*)d_in[0];
    const float* x_ref  = (const float*)d_in[1];
    const float* w_mic  = (const float*)d_in[2];
    const float* b_mic  = (const float*)d_in[3];
    const float* w_ref  = (const float*)d_in[4];
    const float* b_ref  = (const float*)d_in[5];
    const float* w_conv = (const float*)d_in[6];
    float* out = (float*)d_out;

    k_chanmix<<<2 * Bn * Tn, 256>>>(x_mic, w_mic, b_mic, x_ref, w_ref, b_ref);
    k_corr<<<Bn * Hn * (Tn / 64), 128>>>();
    k_convsoftmax<<<Bn * (Tn / 4), 64>>>(w_conv);
    k_align<<<Bn * Cn * (Tn / 32), 128>>>(x_ref, out);
}

// round 13
// speedup vs baseline: 1.0275x; 1.0275x over previous
#include <cuda_runtime.h>

// AlignBlock on sm_103a, round 13: r11 winner restored (conv r10, align r11)
// + chanmix inner loop c-chunked by 4 so weights come via LDS.128 broadcast
// (issue overhead 31% -> 12.5% over the scalar-FMA floor).
// Shapes: B=2, C=H=64, T=512, F=64, DMAX=32. All fp32.

#define Bn 2
#define Cn 64
#define Hn 64
#define Tn 512
#define Fn 64
#define Dn 32

__device__ float g_Q[Bn * Hn * Tn * Fn];
__device__ float g_K[Bn * Hn * Tn * Fn];
__device__ float g_V[Bn * Hn * Tn * Dn];
__device__ float g_A[Bn * Tn * Dn];

// ---------------------------------------------------------------------------
// Kernel 1: channel mix for Q AND K (merged).
// out[b,h,t,f] = sum_c w[h,c] * x[b,c,t,f] + bias[h]
// grid = 2*B*T = 2048 blocks, 256 threads. Thread tile 4h x 4f.
// Inner loop: c in chunks of 4 -> per chunk 4 w-LDS.128 (natural [h][c],
// warp-broadcast) + 4 x-LDS.128 + 64 FFMA (12.5% issue overhead).
// ---------------------------------------------------------------------------
__global__ void __launch_bounds__(256) k_chanmix(const float* __restrict__ xm,
                                                 const float* __restrict__ wm,
                                                 const float* __restrict__ bm,
                                                 const float* __restrict__ xr,
                                                 const float* __restrict__ wr,
                                                 const float* __restrict__ br) {
    const int tid = threadIdx.x;
    const int which = blockIdx.x >> 10;
    const int rem = blockIdx.x & 1023;
    const int b = rem >> 9;
    const int t = rem & 511;

    const float* x    = which ? xr : xm;
    const float* w    = which ? wr : wm;
    const float* bias = which ? br : bm;
    float* out        = which ? g_K : g_Q;

    __shared__ float xs[64][68];        // [c][f]
    __shared__ float ws[64][68];        // [h][c]  (natural)

#pragma unroll
    for (int it = 0; it < 4; it++) {
        int idx = tid + it * 256;
        int q4 = (idx & 15) * 4;
        int r  = idx >> 4;
        *(float4*)&xs[r][q4] =
            *(const float4*)&x[((b * 64 + r) * 512 + t) * 64 + q4];
        *(float4*)&ws[r][q4] = *(const float4*)&w[r * 64 + q4];
    }
    __syncthreads();

    const int f0 = (tid & 15) * 4;
    const int h0 = (tid >> 4) * 4;

    float4 acc[4];
#pragma unroll
    for (int a = 0; a < 4; a++) acc[a] = make_float4(0.f, 0.f, 0.f, 0.f);

#pragma unroll 4
    for (int c0 = 0; c0 < 64; c0 += 4) {
        float4 wv[4], xv[4];
#pragma unroll
        for (int a = 0; a < 4; a++) wv[a] = *(const float4*)&ws[h0 + a][c0];
#pragma unroll
        for (int j = 0; j < 4; j++) xv[j] = *(const float4*)&xs[c0 + j][f0];
#pragma unroll
        for (int a = 0; a < 4; a++) {
            float ww[4] = {wv[a].x, wv[a].y, wv[a].z, wv[a].w};
#pragma unroll
            for (int j = 0; j < 4; j++) {
                acc[a].x += ww[j] * xv[j].x;
                acc[a].y += ww[j] * xv[j].y;
                acc[a].z += ww[j] * xv[j].z;
                acc[a].w += ww[j] * xv[j].w;
            }
        }
    }

#pragma unroll
    for (int a = 0; a < 4; a++) {
        float bb = __ldg(&bias[h0 + a]);
        float4 r = acc[a];
        r.x += bb; r.y += bb; r.z += bb; r.w += bb;
        *(float4*)&out[((b * 64 + h0 + a) * 512 + t) * 64 + f0] = r;
    }
}

// ---------------------------------------------------------------------------
// Kernel 2: banded correlation (r9-r11 version, unchanged).
// ---------------------------------------------------------------------------
__global__ void __launch_bounds__(128) k_corr() {
    const int tid = threadIdx.x;
    const int warp = tid >> 5, lane = tid & 31;
    const int t0 = (blockIdx.x & 7) * 64;
    const int h  = (blockIdx.x >> 3) & 63;
    const int b  = blockIdx.x >> 9;

    __shared__ float Qs[64][68];    // [f][i]
    __shared__ float Ks[64][100];   // [f][r]

    const float* qg = g_Q + ((b * 64 + h) * 512 + t0) * 64;
    const float* kg = g_K + ((b * 64 + h) * 512) * 64;

#pragma unroll
    for (int it = 0; it < 4; it++) {
        int fq = warp * 4 + it;
#pragma unroll
        for (int sub = 0; sub < 2; sub++) {
            int i = lane + sub * 32;
            float4 v = *(const float4*)&qg[i * 64 + fq * 4];
            Qs[4 * fq + 0][i] = v.x;
            Qs[4 * fq + 1][i] = v.y;
            Qs[4 * fq + 2][i] = v.z;
            Qs[4 * fq + 3][i] = v.w;
        }
    }
#pragma unroll
    for (int it = 0; it < 4; it++) {
        int fq = warp * 4 + it;
#pragma unroll
        for (int sub = 0; sub < 3; sub++) {
            int r = lane + sub * 32;
            if (r < 95) {
                int tr = t0 - 31 + r;
                float4 v = make_float4(0.f, 0.f, 0.f, 0.f);
                if (tr >= 0) v = *(const float4*)&kg[tr * 64 + fq * 4];
                Ks[4 * fq + 0][r] = v.x;
                Ks[4 * fq + 1][r] = v.y;
                Ks[4 * fq + 2][r] = v.z;
                Ks[4 * fq + 3][r] = v.w;
            }
        }
    }
    __syncthreads();

    const int d0 = (tid & 7) * 4;
    const int i0 = (tid >> 3) * 4;

    float acc[4][4];
#pragma unroll
    for (int a = 0; a < 4; a++)
#pragma unroll
        for (int e = 0; e < 4; e++) acc[a][e] = 0.f;

#pragma unroll 8
    for (int f = 0; f < 64; f++) {
        float4 q4 = *(const float4*)&Qs[f][i0];
        float4 k0 = *(const float4*)&Ks[f][i0 + d0];
        float4 k1 = *(const float4*)&Ks[f][i0 + d0 + 4];
        float qq[4] = {q4.x, q4.y, q4.z, q4.w};
        float kk[8] = {k0.x, k0.y, k0.z, k0.w, k1.x, k1.y, k1.z, k1.w};
#pragma unroll
        for (int a = 0; a < 4; a++)
#pragma unroll
            for (int e = 0; e < 4; e++)
                acc[a][e] += qq[a] * kk[a + e];
    }

    float* vg = g_V + ((b * 64 + h) * 512 + t0) * 32;
#pragma unroll
    for (int a = 0; a < 4; a++) {
        float4 r = make_float4(acc[a][0] * 0.125f, acc[a][1] * 0.125f,
                               acc[a][2] * 0.125f, acc[a][3] * 0.125f);
        *(float4*)&vg[(i0 + a) * 32 + d0] = r;
    }
}

// ---------------------------------------------------------------------------
// Kernel 3: (5,3) conv over (T,dmax) reducing H->1, + softmax over dmax.
// (r10 version: 128 threads, t-tile 8 — measured best)
// ---------------------------------------------------------------------------
__global__ void __launch_bounds__(128) k_convsoftmax(const float* __restrict__ wconv) {
    const int tid = threadIdx.x;
    const int b  = blockIdx.x >> 6;
    const int t0 = (blockIdx.x & 63) * 8;

    __shared__ float Vs[16][12][34];
    __shared__ float wcs[64][16];
    __shared__ float red[8][33];

    for (int idx = tid; idx < 960; idx += 128)
        wcs[idx / 15][idx % 15] = wconv[idx];
    for (int idx = tid; idx < 16 * 12; idx += 128) {
        Vs[idx / 12][idx % 12][0]  = 0.0f;
        Vs[idx / 12][idx % 12][33] = 0.0f;
    }

    const int tl = tid >> 4;
    const int d  = (tid & 15) * 2;

    float accA0 = 0.f, accA1 = 0.f, accB0 = 0.f, accB1 = 0.f;

    for (int hc = 0; hc < 4; hc++) {
        __syncthreads();
        for (int g = tid; g < 1536; g += 128) {
            int dq = g & 7;
            int hr = g >> 3;
            int r  = hr % 12;
            int hl = hr / 12;
            int tt = t0 - 4 + r;
            float4 v = make_float4(0.f, 0.f, 0.f, 0.f);
            if (tt >= 0)
                v = *(const float4*)&g_V[((b * 64 + hc * 16 + hl) * 512 + tt) * 32 + dq * 4];
            Vs[hl][r][1 + dq * 4 + 0] = v.x;
            Vs[hl][r][1 + dq * 4 + 1] = v.y;
            Vs[hl][r][1 + dq * 4 + 2] = v.z;
            Vs[hl][r][1 + dq * 4 + 3] = v.w;
        }
        __syncthreads();

#pragma unroll 2
        for (int hl = 0; hl < 16; hl++) {
            int hh = hc * 16 + hl;
            float wreg[16];
#pragma unroll
            for (int k4 = 0; k4 < 4; k4++) {
                float4 wv = *(const float4*)&wcs[hh][k4 * 4];
                wreg[k4 * 4 + 0] = wv.x; wreg[k4 * 4 + 1] = wv.y;
                wreg[k4 * 4 + 2] = wv.z; wreg[k4 * 4 + 3] = wv.w;
            }
#pragma unroll
            for (int i = 0; i < 5; i++) {
                float2 u = *(const float2*)&Vs[hl][tl + i][d];
                float2 v = *(const float2*)&Vs[hl][tl + i][d + 2];
                float w0 = wreg[i * 3], w1 = wreg[i * 3 + 1], w2 = wreg[i * 3 + 2];
                if (i & 1) {
                    accB0 += u.x * w0 + u.y * w1 + v.x * w2;
                    accB1 += u.y * w0 + v.x * w1 + v.y * w2;
                } else {
                    accA0 += u.x * w0 + u.y * w1 + v.x * w2;
                    accA1 += u.y * w0 + v.x * w1 + v.y * w2;
                }
            }
        }
    }

    red[tl][d]     = accA0 + accB0;
    red[tl][d + 1] = accA1 + accB1;
    __syncthreads();

    const int wd = tid >> 5, lane = tid & 31;
#pragma unroll
    for (int rr = 0; rr < 2; rr++) {
        int row = wd * 2 + rr;
        float v = red[row][lane];
        float mx = v;
#pragma unroll
        for (int o = 16; o > 0; o >>= 1)
            mx = fmaxf(mx, __shfl_xor_sync(0xffffffffu, mx, o));
        float e = __expf(v - mx);
        float s = e;
#pragma unroll
        for (int o = 16; o > 0; o >>= 1)
            s += __shfl_xor_sync(0xffffffffu, s, o);
        g_A[(b * 512 + t0 + row) * 32 + lane] = e / s;
    }
}

// ---------------------------------------------------------------------------
// Kernel 4: aligned[b,c,t,f] = sum_d A[b,t,d] * x_ref[b,c,t-31+d,f]
// (r11 version: gmem-direct X, measured 15.9us)
// ---------------------------------------------------------------------------
__device__ __forceinline__ void align_body(const float* __restrict__ xg,
                                           const float (*As)[36],
                                           float4* acc, int i0, int tbase,
                                           bool guard) {
#pragma unroll
    for (int d0 = 0; d0 < 32; d0 += 4) {
        float4 av[4];
#pragma unroll
        for (int a = 0; a < 4; a++) av[a] = *(const float4*)&As[i0 + a][d0];
        float4 xv[7];
#pragma unroll
        for (int k = 0; k < 7; k++) {
            int tg = tbase + d0 + k;
            if (guard)
                xv[k] = (tg >= 0) ? *(const float4*)&xg[tg * 64]
                                  : make_float4(0.f, 0.f, 0.f, 0.f);
            else
                xv[k] = *(const float4*)&xg[tg * 64];
        }
#pragma unroll
        for (int a = 0; a < 4; a++) {
            float aa[4] = {av[a].x, av[a].y, av[a].z, av[a].w};
#pragma unroll
            for (int dd = 0; dd < 4; dd++) {
                float4 x4 = xv[a + dd];
                acc[a].x += aa[dd] * x4.x;
                acc[a].y += aa[dd] * x4.y;
                acc[a].z += aa[dd] * x4.z;
                acc[a].w += aa[dd] * x4.w;
            }
        }
    }
}

__global__ void __launch_bounds__(128) k_align(const float* __restrict__ xref,
                                               float* __restrict__ out) {
    const int tid = threadIdx.x;
    const int t0 = (blockIdx.x & 15) * 32;
    const int c  = (blockIdx.x >> 4) & 63;
    const int b  = blockIdx.x >> 10;

    __shared__ float As[32][36];

    const float* ag = g_A + (b * 512 + t0) * 32;
#pragma unroll
    for (int it = 0; it < 2; it++) {
        int idx = tid + it * 128;
        int i = idx >> 3, dq = idx & 7;
        *(float4*)&As[i][dq * 4] = *(const float4*)&ag[i * 32 + dq * 4];
    }
    __syncthreads();

    const int f0 = (tid & 15) * 4;
    const int i0 = (tid >> 4) * 4;
    const int tbase = t0 + i0 - 31;

    const float* xg = xref + ((b * 64 + c) * 512) * 64 + f0;

    float4 acc[4];
#pragma unroll
    for (int a = 0; a < 4; a++) acc[a] = make_float4(0.f, 0.f, 0.f, 0.f);

    if (t0 == 0)
        align_body(xg, As, acc, i0, tbase, true);
    else
        align_body(xg, As, acc, i0, tbase, false);

    float* og = out + ((b * 64 + c) * 512 + t0) * 64;
#pragma unroll
    for (int a = 0; a < 4; a++)
        *(float4*)&og[(i0 + a) * 64 + f0] = acc[a];
}

// ---------------------------------------------------------------------------
extern "C" void kernel_launch(void* const* d_in, const int* in_sizes, int n_in,
                              void* d_out, int out_size) {
    (void)in_sizes; (void)n_in; (void)out_size;
    const float* x_mic  = (const float*)d_in[0];
    const float* x_ref  = (const float*)d_in[1];
    const float* w_mic  = (const float*)d_in[2];
    const float* b_mic  = (const float*)d_in[3];
    const float* w_ref  = (const float*)d_in[4];
    const float* b_ref  = (const float*)d_in[5];
    const float* w_conv = (const float*)d_in[6];
    float* out = (float*)d_out;

    k_chanmix<<<2 * Bn * Tn, 256>>>(x_mic, w_mic, b_mic, x_ref, w_ref, b_ref);
    k_corr<<<Bn * Hn * (Tn / 64), 128>>>();
    k_convsoftmax<<<Bn * (Tn / 8), 128>>>(w_conv);
    k_align<<<Bn * Cn * (Tn / 32), 128>>>(x_ref, out);
}